// round 4
// baseline (speedup 1.0000x reference)
#include <cuda_runtime.h>
#include <cuda_bf16.h>

// GCN layer via on-the-fly CSR:
//   out[s] = norm[s] * sum_{e: src=s} ew[e] * (norm[dst]*(features@K))[dst[e]] + bias
// Pipeline:
//   1) zero int degree counters
//   2) degree histogram over srcs (int RED)
//   3) single-block exclusive scan -> rowptr + cursor
//   4) scatter: pos = atomicAdd(cursor[src]); sorted[pos] = {dst, w}
//   5) transform: h' = (features @ K) * rsqrt(max(deg,1))
//   6) warp-per-node gather-reduce: acc += w * h'[dst]; out = acc*norm + bias
//
// Inputs: features f32[100000,32], edge_srcs i32[E], edge_dsts i32[E],
// edge_weights f32[E], kernels f32[32,32], biases f32[32]. Output f32[100000,32].

#define NUM_NODES 100000
#define F 32
#define E_MAX 3200000
#define SCAN_THREADS 1024

// Static scratch (no allocations allowed)
__device__ __align__(16) float g_h[NUM_NODES * F];      // h' = norm * (features @ K)
__device__ int  g_deg[NUM_NODES];
__device__ int  g_rowptr[NUM_NODES + 1];
__device__ int  g_cursor[NUM_NODES];
__device__ __align__(8) int2 g_sorted[E_MAX];           // {dst, __float_as_int(w)}

// ---------------------------------------------------------------------------
__global__ void zero_deg_kernel(int n) {
    int i = blockIdx.x * blockDim.x + threadIdx.x;
    if (i < n) g_deg[i] = 0;
}

__global__ void deg_kernel(const int* __restrict__ srcs, int E) {
    int e = blockIdx.x * blockDim.x + threadIdx.x;
    if (e < E) atomicAdd(&g_deg[srcs[e]], 1);   // no return use -> REDG
}

// Single-block exclusive scan of g_deg into g_rowptr (and g_cursor copy).
// Each thread handles a contiguous chunk of CEIL(N/1024) elements.
__global__ void scan_kernel(int N) {
    __shared__ int warp_sums[32];
    const int PER = (NUM_NODES + SCAN_THREADS - 1) / SCAN_THREADS;  // 98
    int t    = threadIdx.x;
    int lane = t & 31;
    int wid  = t >> 5;
    int base = t * PER;

    // local sum
    int sum = 0;
    for (int i = 0; i < PER; ++i) {
        int idx = base + i;
        if (idx < N) sum += g_deg[idx];
    }

    // warp inclusive scan
    int v = sum;
#pragma unroll
    for (int off = 1; off < 32; off <<= 1) {
        int o = __shfl_up_sync(0xffffffffu, v, off);
        if (lane >= off) v += o;
    }
    if (lane == 31) warp_sums[wid] = v;
    __syncthreads();

    // scan warp sums (warp 0)
    if (wid == 0) {
        int ws = (lane < SCAN_THREADS / 32) ? warp_sums[lane] : 0;
#pragma unroll
        for (int off = 1; off < 32; off <<= 1) {
            int o = __shfl_up_sync(0xffffffffu, ws, off);
            if (lane >= off) ws += o;
        }
        warp_sums[lane] = ws;
    }
    __syncthreads();

    int excl = v - sum + (wid > 0 ? warp_sums[wid - 1] : 0);  // exclusive prefix for this thread

    // write prefix values
    int run = excl;
    for (int i = 0; i < PER; ++i) {
        int idx = base + i;
        if (idx < N) {
            g_rowptr[idx] = run;
            g_cursor[idx] = run;
            run += g_deg[idx];
        }
    }
    if (t == SCAN_THREADS - 1) g_rowptr[N] = run;
}

// scatter edges into CSR order
__global__ void scatter_kernel(const int* __restrict__ srcs,
                               const int* __restrict__ dsts,
                               const float* __restrict__ ew,
                               int E) {
    int e = blockIdx.x * blockDim.x + threadIdx.x;
    if (e >= E) return;
    int s = __ldg(srcs + e);
    int pos = atomicAdd(&g_cursor[s], 1);
    g_sorted[pos] = make_int2(__ldg(dsts + e), __float_as_int(__ldg(ew + e)));
}

// transform: one warp per node; lane f computes (features[n] @ K)[:,f] * norm[n]
__global__ void transform_kernel(const float* __restrict__ features,
                                 const float* __restrict__ kernels,
                                 int N) {
    __shared__ float sk[F * F];
    for (int i = threadIdx.x; i < F * F; i += blockDim.x)
        sk[i] = kernels[i];
    __syncthreads();

    int gwarp = (blockIdx.x * blockDim.x + threadIdx.x) >> 5;
    int lane  = threadIdx.x & 31;
    if (gwarp >= N) return;

    float feat = features[gwarp * F + lane];
    float acc = 0.0f;
#pragma unroll
    for (int k = 0; k < F; ++k)
        acc = fmaf(__shfl_sync(0xffffffffu, feat, k), sk[k * F + lane], acc);

    float nrm = rsqrtf(fmaxf((float)g_deg[gwarp], 1.0f));
    g_h[gwarp * F + lane] = acc * nrm;
}

// warp-per-node gather reduce. lanes: eg = lane>>3 (edge slot 0..3), c = lane&7 (chunk).
// Processes up to 8 edges per loop iteration (2-deep manual unroll for MLP).
__global__ void gather_kernel(const float* __restrict__ biases,
                              float* __restrict__ out, int N) {
    int warp = (blockIdx.x * blockDim.x + threadIdx.x) >> 5;
    int lane = threadIdx.x & 31;
    if (warp >= N) return;

    int start = g_rowptr[warp];
    int end   = g_rowptr[warp + 1];
    int eg = lane >> 3;
    int c  = lane & 7;

    float4 acc = make_float4(0.f, 0.f, 0.f, 0.f);
    const float4* hp = reinterpret_cast<const float4*>(g_h);

    for (int i = start + eg; i < end; i += 8) {
        int2 pa = __ldg(&g_sorted[i]);
        int  j  = i + 4;
        bool jb = j < end;
        int2 pb = jb ? __ldg(&g_sorted[j]) : make_int2(0, 0);

        float  wa = __int_as_float(pa.y);
        float4 va = __ldg(hp + (size_t)pa.x * 8 + c);
        acc.x = fmaf(wa, va.x, acc.x);
        acc.y = fmaf(wa, va.y, acc.y);
        acc.z = fmaf(wa, va.z, acc.z);
        acc.w = fmaf(wa, va.w, acc.w);

        if (jb) {
            float  wb = __int_as_float(pb.y);
            float4 vb = __ldg(hp + (size_t)pb.x * 8 + c);
            acc.x = fmaf(wb, vb.x, acc.x);
            acc.y = fmaf(wb, vb.y, acc.y);
            acc.z = fmaf(wb, vb.z, acc.z);
            acc.w = fmaf(wb, vb.w, acc.w);
        }
    }

    // butterfly-reduce across the 4 edge slots (xor 8, 16)
#pragma unroll
    for (int off = 8; off <= 16; off <<= 1) {
        acc.x += __shfl_xor_sync(0xffffffffu, acc.x, off);
        acc.y += __shfl_xor_sync(0xffffffffu, acc.y, off);
        acc.z += __shfl_xor_sync(0xffffffffu, acc.z, off);
        acc.w += __shfl_xor_sync(0xffffffffu, acc.w, off);
    }

    if (lane < 8) {
        float nrm = rsqrtf(fmaxf((float)g_deg[warp], 1.0f));
        float4 b  = reinterpret_cast<const float4*>(biases)[lane];
        float4 r;
        r.x = fmaf(acc.x, nrm, b.x);
        r.y = fmaf(acc.y, nrm, b.y);
        r.z = fmaf(acc.z, nrm, b.z);
        r.w = fmaf(acc.w, nrm, b.w);
        reinterpret_cast<float4*>(out)[(size_t)warp * 8 + lane] = r;
    }
}

extern "C" void kernel_launch(void* const* d_in, const int* in_sizes, int n_in,
                              void* d_out, int out_size) {
    const float* features = (const float*)d_in[0];
    const int*   srcs     = (const int*)d_in[1];
    const int*   dsts     = (const int*)d_in[2];
    const float* ew       = (const float*)d_in[3];
    const float* kernels  = (const float*)d_in[4];
    const float* biases   = (const float*)d_in[5];
    float*       out      = (float*)d_out;

    int N = in_sizes[0] / F;   // 100000
    int E = in_sizes[1];       // 3200000

    {
        int threads = 256;
        zero_deg_kernel<<<(N + threads - 1) / threads, threads>>>(N);
    }
    {
        int threads = 256;
        deg_kernel<<<(E + threads - 1) / threads, threads>>>(srcs, E);
    }
    scan_kernel<<<1, SCAN_THREADS>>>(N);
    {
        int threads = 256;
        scatter_kernel<<<(E + threads - 1) / threads, threads>>>(srcs, dsts, ew, E);
    }
    {
        int threads = 256;  // 8 warps = 8 nodes per block
        int nodes_per_block = threads / 32;
        int blocks = (N + nodes_per_block - 1) / nodes_per_block;
        transform_kernel<<<blocks, threads>>>(features, kernels, N);
    }
    {
        int threads = 256;
        int nodes_per_block = threads / 32;
        int blocks = (N + nodes_per_block - 1) / nodes_per_block;
        gather_kernel<<<blocks, threads>>>(biases, out, N);
    }
}

// round 5
// speedup vs baseline: 2.2532x; 2.2532x over previous
#include <cuda_runtime.h>
#include <cuda_bf16.h>

// GCN layer (R2 structure, edge kernel with 4-way edge ILP):
//   1) memset deg=0, memset out=0
//   2) deg histogram over srcs (float RED, 4 edges/thread)
//   3) h' = (features @ K) * rsqrt(max(deg,1));  store norm
//   4) edge scatter: out[src] += ew * h'[dst]   (red.global.add.v4.f32,
//      4 independent edges per thread -> 4 gathers in flight before REDs)
//   5) out = out * norm[src] + bias  (float4)
//
// Inputs: features f32[100000,32], edge_srcs i32[E], edge_dsts i32[E],
// edge_weights f32[E], kernels f32[32,32], biases f32[32]. Output f32[100000,32].

#define NUM_NODES 100000
#define F 32

__device__ __align__(16) float g_h[NUM_NODES * F];   // h' = norm * (features @ K)
__device__ float g_norm[NUM_NODES];
__device__ float g_deg[NUM_NODES];

// ---------------------------------------------------------------------------
// degree histogram: 4 edges per thread, coalesced index loads
__global__ __launch_bounds__(512) void deg_kernel(const int* __restrict__ srcs, int E) {
    int t = blockIdx.x * blockDim.x + threadIdx.x;
    int base = t * 4;
#pragma unroll
    for (int k = 0; k < 4; ++k) {
        int e = base + k;
        if (e < E) atomicAdd(&g_deg[srcs[e]], 1.0f);   // no return use -> REDG
    }
}

// transform: one warp per node; lane f computes (features[n] @ K)[:,f] * norm[n]
__global__ void transform_kernel(const float* __restrict__ features,
                                 const float* __restrict__ kernels,
                                 int N) {
    __shared__ float sk[F * F];
    for (int i = threadIdx.x; i < F * F; i += blockDim.x)
        sk[i] = kernels[i];
    __syncthreads();

    int gwarp = (blockIdx.x * blockDim.x + threadIdx.x) >> 5;
    int lane  = threadIdx.x & 31;
    if (gwarp >= N) return;

    float feat = features[gwarp * F + lane];
    float acc = 0.0f;
#pragma unroll
    for (int k = 0; k < F; ++k)
        acc = fmaf(__shfl_sync(0xffffffffu, feat, k), sk[k * F + lane], acc);

    float nrm = rsqrtf(fmaxf(g_deg[gwarp], 1.0f));
    g_h[gwarp * F + lane] = acc * nrm;
    if (lane == 0) g_norm[gwarp] = nrm;
}

// edge scatter: 8 threads per edge-slot, 4 edges per thread (e, e+Q, e+2Q, e+3Q).
// All gathers issued before any RED (asm memory clobber pins ordering).
__global__ __launch_bounds__(512) void edge_kernel(const int* __restrict__ srcs,
                                                   const int* __restrict__ dsts,
                                                   const float* __restrict__ ew,
                                                   float* __restrict__ out,
                                                   int E, int Q) {
    int t = blockIdx.x * blockDim.x + threadIdx.x;
    int e = t >> 3;
    int c = t & 7;
    if (e >= Q) return;

    int   se[4], de[4];
    float we[4];
    bool  ok[4];
#pragma unroll
    for (int k = 0; k < 4; ++k) {
        int ee = e + k * Q;
        ok[k] = ee < E;
        if (ok[k]) {
            se[k] = __ldg(srcs + ee);
            de[k] = __ldg(dsts + ee);
            we[k] = __ldg(ew + ee);
        } else {
            se[k] = 0; de[k] = 0; we[k] = 0.0f;
        }
    }

    const float4* hp = reinterpret_cast<const float4*>(g_h);
    float4 v[4];
#pragma unroll
    for (int k = 0; k < 4; ++k)
        if (ok[k]) v[k] = __ldg(hp + (size_t)de[k] * 8 + c);

    float4* op = reinterpret_cast<float4*>(out);
#pragma unroll
    for (int k = 0; k < 4; ++k) {
        if (ok[k]) {
            float4* p = op + (size_t)se[k] * 8 + c;
            asm volatile(
                "red.global.add.v4.f32 [%0], {%1, %2, %3, %4};"
                :: "l"(p), "f"(v[k].x * we[k]), "f"(v[k].y * we[k]),
                   "f"(v[k].z * we[k]), "f"(v[k].w * we[k])
                : "memory");
        }
    }
}

// finalize: out4 = out4 * norm[n] + bias4  (float4, one chunk per thread)
__global__ __launch_bounds__(512) void finalize_kernel(float* __restrict__ out,
                                                       const float* __restrict__ biases,
                                                       int N) {
    int t = blockIdx.x * blockDim.x + threadIdx.x;
    int n = t >> 3;
    int c = t & 7;
    if (n >= N) return;
    float nrm = g_norm[n];
    float4 b  = reinterpret_cast<const float4*>(biases)[c];
    float4* p = reinterpret_cast<float4*>(out) + (size_t)n * 8 + c;
    float4 v  = *p;
    v.x = fmaf(v.x, nrm, b.x);
    v.y = fmaf(v.y, nrm, b.y);
    v.z = fmaf(v.z, nrm, b.z);
    v.w = fmaf(v.w, nrm, b.w);
    *p = v;
}

extern "C" void kernel_launch(void* const* d_in, const int* in_sizes, int n_in,
                              void* d_out, int out_size) {
    const float* features = (const float*)d_in[0];
    const int*   srcs     = (const int*)d_in[1];
    const int*   dsts     = (const int*)d_in[2];
    const float* ew       = (const float*)d_in[3];
    const float* kernels  = (const float*)d_in[4];
    const float* biases   = (const float*)d_in[5];
    float*       out      = (float*)d_out;

    int N = in_sizes[0] / F;   // 100000
    int E = in_sizes[1];       // 3200000

    // zero accumulators (int 0 bits == 0.0f)
    cudaMemsetAsync(d_out, 0, (size_t)out_size * sizeof(float));
    {
        void* degp = nullptr;
        cudaGetSymbolAddress(&degp, g_deg);
        cudaMemsetAsync(degp, 0, (size_t)N * sizeof(float));
    }

    {
        int threads = 512;
        int work = (E + 3) / 4;
        deg_kernel<<<(work + threads - 1) / threads, threads>>>(srcs, E);
    }
    {
        int threads = 256;                  // 8 warps = 8 nodes per block
        int blocks = (N + 7) / 8;
        transform_kernel<<<blocks, threads>>>(features, kernels, N);
    }
    {
        int Q = (E + 3) / 4;                // edges per ILP slot
        int threads = 512;
        long long total = (long long)Q * 8; // 8 threads per edge-slot
        int blocks = (int)((total + threads - 1) / threads);
        edge_kernel<<<blocks, threads>>>(srcs, dsts, ew, out, E, Q);
    }
    {
        int threads = 512;
        long long total = (long long)N * 8;
        int blocks = (int)((total + threads - 1) / threads);
        finalize_kernel<<<blocks, threads>>>(out, biases, N);
    }
}